// round 1
// baseline (speedup 1.0000x reference)
#include <cuda_runtime.h>
#include <math.h>

// Problem constants (fixed shapes)
#define BATCH 2
#define SEQ   2048
#define HID   2048
#define NH    16
#define NKV   4
#define GRP   4
#define HD    128
#define MROWS (BATCH*SEQ)     // 4096

// ---------------- scratch (device globals; no allocation allowed) ----------
__device__ float g_Pl1[MROWS*HID];
__device__ float g_P  [MROWS*HID];
__device__ float g_Q  [MROWS*HID];        // [B*NH, S, HD]
__device__ float g_K  [MROWS*(NKV*HD)];   // [B*NKV, S, HD]
__device__ float g_V  [MROWS*(NKV*HD)];   // [B*NKV, S, HD]
__device__ float g_ctx[MROWS*HID];        // [B*S, H]
__device__ float g_pre[MROWS*HID];        // pre-layernorm

// ---------------- SGEMM: C = A @ B + bias, with epilogue modes -------------
// mode 0: relu      -> C[r*N+c]
// mode 1: + res     -> C[r*N+c]
// mode 2: head scatter -> C[((b*heads+head)*S + s)*HD + d]
// mode 3: plain     -> C[r*N+c]
__global__ __launch_bounds__(256, 2)
void sgemm_kernel(const float* __restrict__ A, const float* __restrict__ B,
                  const float* __restrict__ bias, const float* __restrict__ res,
                  float* __restrict__ C,
                  int M, int N, int K, int mode, int heads)
{
    __shared__ float As[16][132];   // [k][m], padded
    __shared__ float Bs[16][128];   // [k][n]

    const int tid = threadIdx.x;
    const int tx  = tid & 15;
    const int ty  = tid >> 4;

    const int aM = tid >> 2;          // 0..63
    const int aK = (tid & 3) << 2;    // 0,4,8,12
    const int bN = (tid & 31) << 2;   // 0..124
    const int bK = tid >> 5;          // 0..7

    const float* Ap = A + (size_t)(blockIdx.y * 128 + aM) * K + aK;
    const float* Bp = B + (size_t)bK * N + blockIdx.x * 128 + bN;

    float acc[8][8];
    #pragma unroll
    for (int i = 0; i < 8; i++)
        #pragma unroll
        for (int j = 0; j < 8; j++) acc[i][j] = 0.f;

    for (int k0 = 0; k0 < K; k0 += 16) {
        float4 a0 = *(const float4*)Ap;
        float4 a1 = *(const float4*)(Ap + (size_t)64 * K);
        float4 b0 = *(const float4*)Bp;
        float4 b1 = *(const float4*)(Bp + (size_t)8 * N);

        As[aK+0][aM]    = a0.x; As[aK+1][aM]    = a0.y;
        As[aK+2][aM]    = a0.z; As[aK+3][aM]    = a0.w;
        As[aK+0][aM+64] = a1.x; As[aK+1][aM+64] = a1.y;
        As[aK+2][aM+64] = a1.z; As[aK+3][aM+64] = a1.w;
        *(float4*)&Bs[bK][bN]   = b0;
        *(float4*)&Bs[bK+8][bN] = b1;
        __syncthreads();

        #pragma unroll
        for (int k = 0; k < 16; k++) {
            float ra[8], rb[8];
            *(float4*)&ra[0] = *(const float4*)&As[k][ty*8];
            *(float4*)&ra[4] = *(const float4*)&As[k][ty*8+4];
            *(float4*)&rb[0] = *(const float4*)&Bs[k][tx*8];
            *(float4*)&rb[4] = *(const float4*)&Bs[k][tx*8+4];
            #pragma unroll
            for (int i = 0; i < 8; i++)
                #pragma unroll
                for (int j = 0; j < 8; j++)
                    acc[i][j] = fmaf(ra[i], rb[j], acc[i][j]);
        }
        __syncthreads();
        Ap += 16;
        Bp += (size_t)16 * N;
    }

    const int row0 = blockIdx.y * 128 + ty * 8;
    const int col0 = blockIdx.x * 128 + tx * 8;
    #pragma unroll
    for (int i = 0; i < 8; i++) {
        int r = row0 + i;
        #pragma unroll
        for (int j = 0; j < 8; j++) {
            int c = col0 + j;
            float v = acc[i][j] + bias[c];
            if (mode == 0) {
                C[(size_t)r * N + c] = fmaxf(v, 0.f);
            } else if (mode == 1) {
                C[(size_t)r * N + c] = v + res[(size_t)r * N + c];
            } else if (mode == 3) {
                C[(size_t)r * N + c] = v;
            } else {
                int b = r / SEQ, s = r - b * SEQ;
                int head = c >> 7, d = c & 127;
                C[(((size_t)(b * heads + head)) * SEQ + s) * HD + d] = v;
            }
        }
    }
}

// ---------------- Flash attention (fp32, online softmax) -------------------
// Q: [B*NH, S, HD], K/V: [B*NKV, S, HD], ctx out: [B*S, H]
// Block: 64 query rows per block, 256 threads. Chunks of 64 kv rows.
#define QP 132   // padded row pitch for Q/K/V smem tiles
#define PP 68    // padded pitch for score tile

__global__ __launch_bounds__(256, 1)
void flash_kernel(const float* __restrict__ Q, const float* __restrict__ Kt,
                  const float* __restrict__ Vt, float* __restrict__ ctx)
{
    extern __shared__ float sm[];
    float* Qs     = sm;                 // 64*132
    float* KVs    = Qs  + 64 * QP;      // 64*132 (K then V, reused)
    float* Ps     = KVs + 64 * QP;      // 64*68
    float* alphas = Ps  + 64 * PP;      // 64
    float* ls     = alphas + 64;        // 64

    const int qb = blockIdx.x;          // query tile
    const int bh = blockIdx.y;          // b*NH + h
    const int b  = bh / NH;
    const int h  = bh % NH;
    const int kv = h / GRP;

    const float* Qb = Q  + ((size_t)bh * SEQ + qb * 64) * HD;
    const float* Kb = Kt + ((size_t)(b * NKV + kv) * SEQ) * HD;
    const float* Vb = Vt + ((size_t)(b * NKV + kv) * SEQ) * HD;

    const int tid = threadIdx.x;
    const int tx  = tid & 15;
    const int ty  = tid >> 4;

    // load Q tile (64 x 128)
    #pragma unroll
    for (int t = 0; t < 8; t++) {
        int idx4 = tid + t * 256;       // 0..2047 float4 slots
        int r  = idx4 >> 5;
        int c4 = (idx4 & 31) << 2;
        *(float4*)&Qs[r * QP + c4] = *(const float4*)(Qb + (size_t)r * HD + c4);
    }

    float m_row = -INFINITY, l_row = 0.f;   // valid on tid < 64
    float o[4][8];
    #pragma unroll
    for (int i = 0; i < 4; i++)
        #pragma unroll
        for (int c = 0; c < 8; c++) o[i][c] = 0.f;

    const float scale = 0.08838834764831845f;  // 1/sqrt(128)

    for (int kc = 0; kc < SEQ; kc += 64) {
        __syncthreads();   // prev O-GEMM (and Q load) complete before KVs overwrite
        // load K chunk
        #pragma unroll
        for (int t = 0; t < 8; t++) {
            int idx4 = tid + t * 256;
            int r  = idx4 >> 5;
            int c4 = (idx4 & 31) << 2;
            *(float4*)&KVs[r * QP + c4] =
                *(const float4*)(Kb + (size_t)(kc + r) * HD + c4);
        }
        __syncthreads();

        // scores: 64x64 = Q (64x128) @ K^T
        float sacc[4][4];
        #pragma unroll
        for (int i = 0; i < 4; i++)
            #pragma unroll
            for (int j = 0; j < 4; j++) sacc[i][j] = 0.f;
        for (int d = 0; d < HD; d += 4) {
            float4 qv[4], kv4[4];
            #pragma unroll
            for (int i = 0; i < 4; i++)
                qv[i] = *(const float4*)&Qs[(ty * 4 + i) * QP + d];
            #pragma unroll
            for (int j = 0; j < 4; j++)
                kv4[j] = *(const float4*)&KVs[(tx * 4 + j) * QP + d];
            #pragma unroll
            for (int i = 0; i < 4; i++)
                #pragma unroll
                for (int j = 0; j < 4; j++) {
                    sacc[i][j] = fmaf(qv[i].x, kv4[j].x, sacc[i][j]);
                    sacc[i][j] = fmaf(qv[i].y, kv4[j].y, sacc[i][j]);
                    sacc[i][j] = fmaf(qv[i].z, kv4[j].z, sacc[i][j]);
                    sacc[i][j] = fmaf(qv[i].w, kv4[j].w, sacc[i][j]);
                }
        }
        #pragma unroll
        for (int i = 0; i < 4; i++)
            #pragma unroll
            for (int j = 0; j < 4; j++)
                Ps[(ty * 4 + i) * PP + tx * 4 + j] = sacc[i][j] * scale;
        __syncthreads();

        // online softmax: one thread per row
        if (tid < 64) {
            float rmax = -INFINITY;
            #pragma unroll 8
            for (int j = 0; j < 64; j++) rmax = fmaxf(rmax, Ps[tid * PP + j]);
            float mnew  = fmaxf(m_row, rmax);
            float alpha = expf(m_row - mnew);
            float sum = 0.f;
            #pragma unroll 8
            for (int j = 0; j < 64; j++) {
                float p = expf(Ps[tid * PP + j] - mnew);
                Ps[tid * PP + j] = p;
                sum += p;
            }
            l_row = l_row * alpha + sum;
            m_row = mnew;
            alphas[tid] = alpha;
        }
        __syncthreads();

        // rescale accumulators
        #pragma unroll
        for (int i = 0; i < 4; i++) {
            float a = alphas[ty * 4 + i];
            #pragma unroll
            for (int c = 0; c < 8; c++) o[i][c] *= a;
        }

        // load V chunk into same buffer (K no longer needed)
        #pragma unroll
        for (int t = 0; t < 8; t++) {
            int idx4 = tid + t * 256;
            int r  = idx4 >> 5;
            int c4 = (idx4 & 31) << 2;
            *(float4*)&KVs[r * QP + c4] =
                *(const float4*)(Vb + (size_t)(kc + r) * HD + c4);
        }
        __syncthreads();

        // O += P (64x64) @ V (64x128); this thread: rows ty*4.., cols tx*8..
        for (int j = 0; j < 64; j++) {
            float p[4];
            #pragma unroll
            for (int i = 0; i < 4; i++) p[i] = Ps[(ty * 4 + i) * PP + j];
            float4 v0 = *(const float4*)&KVs[j * QP + tx * 8];
            float4 v1 = *(const float4*)&KVs[j * QP + tx * 8 + 4];
            #pragma unroll
            for (int i = 0; i < 4; i++) {
                o[i][0] = fmaf(p[i], v0.x, o[i][0]);
                o[i][1] = fmaf(p[i], v0.y, o[i][1]);
                o[i][2] = fmaf(p[i], v0.z, o[i][2]);
                o[i][3] = fmaf(p[i], v0.w, o[i][3]);
                o[i][4] = fmaf(p[i], v1.x, o[i][4]);
                o[i][5] = fmaf(p[i], v1.y, o[i][5]);
                o[i][6] = fmaf(p[i], v1.z, o[i][6]);
                o[i][7] = fmaf(p[i], v1.w, o[i][7]);
            }
        }
    }

    __syncthreads();
    if (tid < 64) ls[tid] = l_row;
    __syncthreads();

    #pragma unroll
    for (int i = 0; i < 4; i++) {
        float inv = 1.f / ls[ty * 4 + i];
        int q = qb * 64 + ty * 4 + i;
        float* dst = ctx + ((size_t)(b * SEQ + q)) * HID + h * HD + tx * 8;
        float4 w0 = make_float4(o[i][0]*inv, o[i][1]*inv, o[i][2]*inv, o[i][3]*inv);
        float4 w1 = make_float4(o[i][4]*inv, o[i][5]*inv, o[i][6]*inv, o[i][7]*inv);
        *(float4*)(dst)     = w0;
        *(float4*)(dst + 4) = w1;
    }
}

// ---------------- residual + layernorm -------------------------------------
__device__ __forceinline__ float block_sum256(float v, float* sred)
{
    #pragma unroll
    for (int off = 16; off; off >>= 1) v += __shfl_xor_sync(0xffffffffu, v, off);
    int warp = threadIdx.x >> 5;
    if ((threadIdx.x & 31) == 0) sred[warp] = v;
    __syncthreads();
    if (threadIdx.x < 32) {
        float x = (threadIdx.x < 8) ? sred[threadIdx.x] : 0.f;
        #pragma unroll
        for (int off = 4; off; off >>= 1) x += __shfl_xor_sync(0xffffffffu, x, off);
        if (threadIdx.x == 0) sred[0] = x;
    }
    __syncthreads();
    float r = sred[0];
    __syncthreads();
    return r;
}

__global__ __launch_bounds__(256)
void ln_kernel(const float* __restrict__ x, const float* __restrict__ resid,
               const float* __restrict__ gamma, const float* __restrict__ beta,
               float* __restrict__ out)
{
    __shared__ float sred[32];
    const size_t row = blockIdx.x;
    const int tid = threadIdx.x;
    const float* xr = x     + row * HID;
    const float* rr = resid + row * HID;

    float v[8];
    float s = 0.f;
    #pragma unroll
    for (int t = 0; t < 8; t++) {
        int c = tid + t * 256;
        v[t] = xr[c] + rr[c];
        s += v[t];
    }
    float mean = block_sum256(s, sred) * (1.f / HID);

    float s2 = 0.f;
    #pragma unroll
    for (int t = 0; t < 8; t++) { float d = v[t] - mean; s2 += d * d; }
    float var = block_sum256(s2, sred) * (1.f / HID);
    float rstd = rsqrtf(var + 1e-12f);

    float* orow = out + row * HID;
    #pragma unroll
    for (int t = 0; t < 8; t++) {
        int c = tid + t * 256;
        orow[c] = (v[t] - mean) * rstd * gamma[c] + beta[c];
    }
}

// ---------------- launch ----------------------------------------------------
extern "C" void kernel_launch(void* const* d_in, const int* in_sizes, int n_in,
                              void* d_out, int out_size)
{
    const float* hidden = (const float*)d_in[0];
    const float* src    = (const float*)d_in[1];
    const float* Wq = (const float*)d_in[2];
    const float* bq = (const float*)d_in[3];
    const float* Wk = (const float*)d_in[4];
    const float* bk = (const float*)d_in[5];
    const float* Wv = (const float*)d_in[6];
    const float* bv = (const float*)d_in[7];
    const float* Wd = (const float*)d_in[8];
    const float* bd = (const float*)d_in[9];
    const float* W1 = (const float*)d_in[10];
    const float* b1 = (const float*)d_in[11];
    const float* W2 = (const float*)d_in[12];
    const float* b2 = (const float*)d_in[13];
    const float* gamma = (const float*)d_in[14];
    const float* beta  = (const float*)d_in[15];
    float* out = (float*)d_out;

    float *pPl1, *pP, *pQ, *pK, *pV, *pCtx, *pPre;
    cudaGetSymbolAddress((void**)&pPl1, g_Pl1);
    cudaGetSymbolAddress((void**)&pP,   g_P);
    cudaGetSymbolAddress((void**)&pQ,   g_Q);
    cudaGetSymbolAddress((void**)&pK,   g_K);
    cudaGetSymbolAddress((void**)&pV,   g_V);
    cudaGetSymbolAddress((void**)&pCtx, g_ctx);
    cudaGetSymbolAddress((void**)&pPre, g_pre);

    dim3 blk(256);
    // 1. Pl1 = relu(src @ W1 + b1)
    sgemm_kernel<<<dim3(HID/128, MROWS/128), blk>>>(src, W1, b1, nullptr, pPl1,
                                                    MROWS, HID, HID, 0, 0);
    // 2. P = (Pl1 @ W2 + b2) + Pl1
    sgemm_kernel<<<dim3(HID/128, MROWS/128), blk>>>(pPl1, W2, b2, pPl1, pP,
                                                    MROWS, HID, HID, 1, 0);
    // 3. K = P @ Wk + bk  -> [B*NKV, S, HD]
    sgemm_kernel<<<dim3((NKV*HD)/128, MROWS/128), blk>>>(pP, Wk, bk, nullptr, pK,
                                                    MROWS, NKV*HD, HID, 2, NKV);
    // 4. V = P @ Wv + bv  -> [B*NKV, S, HD]
    sgemm_kernel<<<dim3((NKV*HD)/128, MROWS/128), blk>>>(pP, Wv, bv, nullptr, pV,
                                                    MROWS, NKV*HD, HID, 2, NKV);
    // 5. Q = hidden @ Wq + bq  -> [B*NH, S, HD]
    sgemm_kernel<<<dim3(HID/128, MROWS/128), blk>>>(hidden, Wq, bq, nullptr, pQ,
                                                    MROWS, HID, HID, 2, NH);
    // 6. flash attention -> ctx [B*S, H]
    size_t shmem = (size_t)(64*QP*2 + 64*PP + 128) * sizeof(float);
    cudaFuncSetAttribute(flash_kernel, cudaFuncAttributeMaxDynamicSharedMemorySize,
                         (int)shmem);
    flash_kernel<<<dim3(SEQ/64, BATCH*NH), blk, shmem>>>(pQ, pK, pV, pCtx);
    // 7. pre = ctx @ Wd + bd
    sgemm_kernel<<<dim3(HID/128, MROWS/128), blk>>>(pCtx, Wd, bd, nullptr, pPre,
                                                    MROWS, HID, HID, 3, 0);
    // 8. out = layernorm(pre + hidden)
    ln_kernel<<<MROWS, 256>>>(pPre, hidden, gamma, beta, out);
}